// round 4
// baseline (speedup 1.0000x reference)
#include <cuda_runtime.h>
#include <cstdint>

#define SOM_M    32
#define SOM_N    32
#define MN       1024
#define BATCH    2048
#define DIM      128
#define NITER_F  100.0f
#define ALPHA_F  0.3f
#define SIGMA_F  16.0f

// ---------------- scratch ----------------
__device__ unsigned long long g_part[8][BATCH];  // per-m-block argmin partials
__device__ float g_S[MN * DIM];
__device__ float g_cnt[MN];
__device__ float g_T[MN * DIM];          // [cx][by][d]
__device__ float g_tc[MN];               // [cx][by]

__device__ __forceinline__ unsigned int f2ord(float f) {
    unsigned int u = __float_as_uint(f);
    return (u & 0x80000000u) ? ~u : (u | 0x80000000u);
}

__device__ __forceinline__ void ffma2(unsigned long long& acc,
                                      unsigned long long a,
                                      unsigned long long b) {
    asm("fma.rn.f32x2 %0, %1, %2, %0;" : "+l"(acc) : "l"(a), "l"(b));
}

// ---------------- K1: BMU GEMM + argmin (also zeroes scratch, computes w2) ----
// tile 128m x 128b, 256 threads, 8m x 8b per thread, FFMA2 pairs along K.
// Smem tiles row-natural with 16B-group XOR swizzle for conflict-free reads.
__global__ __launch_bounds__(256, 1)
void k_bmu(const float* __restrict__ x, const float* __restrict__ w) {
    extern __shared__ float smem[];
    float* Ws = smem;                                   // 128*128 f
    float* Xs = smem + 128 * 128;                       // 128*128 f
    unsigned long long* Red =
        (unsigned long long*)(smem + 2 * 128 * 128);    // [16][128]
    float* w2s = (float*)(Red + 16 * 128);              // [128]

    const int m0 = blockIdx.x * 128;
    const int b0 = blockIdx.y * 128;
    const int tid = threadIdx.x;
    const int wrp = tid >> 5, lane = tid & 31;
    const int ty = (lane >> 2) | ((wrp & 1) << 3);      // 0..15
    const int tx = (lane & 3) | ((wrp >> 1) << 2);      // 0..15

    // fold scratch zeroing into this kernel (completes before k_scatter)
    {
        int z = blockIdx.y * 8 + blockIdx.x;            // 0..127
        *(float4*)&g_S[z * 1024 + tid * 4] = make_float4(0.f, 0.f, 0.f, 0.f);
        if (tid < 2)
            *(float4*)&g_cnt[z * 8 + tid * 4] = make_float4(0.f, 0.f, 0.f, 0.f);
    }

    // stage both tiles (LDG.128 -> swizzled ST.128)
    #pragma unroll
    for (int i = 0; i < 16; i++) {
        int idx = tid + i * 256;          // 0..4095
        int row = idx >> 5;               // 0..127
        int g   = idx & 31;               // float4 group
        int sg  = (g ^ ((row >> 3) & 7)) << 2;
        float4 v = *(const float4*)&w[(m0 + row) * DIM + g * 4];
        *(float4*)&Ws[row * 128 + sg] = v;
        float4 u = *(const float4*)&x[(b0 + row) * DIM + g * 4];
        *(float4*)&Xs[row * 128 + sg] = u;
    }
    __syncthreads();

    // w2 from the staged tile (swizzle is a within-row permutation)
    if (tid < 128) {
        float s = 0.0f;
        #pragma unroll
        for (int g = 0; g < 32; g++) {
            float4 v = *(const float4*)&Ws[tid * 128 + g * 4];
            s += v.x * v.x + v.y * v.y + v.z * v.z + v.w * v.w;
        }
        w2s[tid] = s;
    }

    unsigned long long acc[8][8];
    #pragma unroll
    for (int mi = 0; mi < 8; mi++)
        #pragma unroll
        for (int bj = 0; bj < 8; bj++) acc[mi][bj] = 0ULL;

    const float* wbase = &Ws[(ty * 8) * 128];
    const float* xbase = &Xs[(tx * 8) * 128];
    const int sw = ty & 7;
    const int sx = tx & 7;

    #pragma unroll 1
    for (int kt = 0; kt < 32; kt++) {      // 4 k per step
        const int ow = (kt ^ sw) << 2;
        const int ox = (kt ^ sx) << 2;
        ulonglong2 xv[8];
        #pragma unroll
        for (int bj = 0; bj < 8; bj++)
            xv[bj] = *(const ulonglong2*)&xbase[bj * 128 + ox];
        #pragma unroll
        for (int mi = 0; mi < 8; mi++) {
            ulonglong2 wv = *(const ulonglong2*)&wbase[mi * 128 + ow];
            #pragma unroll
            for (int bj = 0; bj < 8; bj++) {
                ffma2(acc[mi][bj], wv.x, xv[bj].x);
                ffma2(acc[mi][bj], wv.y, xv[bj].y);
            }
        }
    }
    __syncthreads();   // w2s ready (and Ws no longer needed)

    float w2r[8];
    #pragma unroll
    for (int mi = 0; mi < 8; mi++) w2r[mi] = w2s[ty * 8 + mi];

    #pragma unroll
    for (int bj = 0; bj < 8; bj++) {
        unsigned long long best = 0xFFFFFFFFFFFFFFFFULL;
        #pragma unroll
        for (int mi = 0; mi < 8; mi++) {
            float lo = __uint_as_float((unsigned int)(acc[mi][bj]));
            float hi = __uint_as_float((unsigned int)(acc[mi][bj] >> 32));
            float d2 = w2r[mi] - 2.0f * (lo + hi);
            unsigned long long key =
                ((unsigned long long)f2ord(d2) << 32) |
                (unsigned long long)(m0 + ty * 8 + mi);
            best = min(best, key);
        }
        Red[ty * 128 + tx * 8 + bj] = best;
    }
    __syncthreads();

    if (tid < 128) {
        unsigned long long best = Red[tid];
        #pragma unroll
        for (int t = 1; t < 16; t++) best = min(best, Red[t * 128 + tid]);
        g_part[blockIdx.x][b0 + tid] = best;   // plain store, no atomics
    }
}

// ---------------- K2: reduce partials + scatter x rows into BMU bins --------
__global__ void k_scatter(const float* __restrict__ x) {
    int warp = (blockIdx.x * blockDim.x + threadIdx.x) >> 5;  // 0..2047
    int lane = threadIdx.x & 31;
    if (warp >= BATCH) return;

    unsigned long long v = (lane < 8) ? g_part[lane][warp]
                                      : 0xFFFFFFFFFFFFFFFFULL;
    #pragma unroll
    for (int o = 4; o >= 1; o >>= 1)
        v = min(v, __shfl_xor_sync(0xffffffffu, v, o));
    v = __shfl_sync(0xffffffffu, v, 0);
    int m = (int)(v & 0xFFFFFFFFULL);

    float4 vv = *(const float4*)&x[warp * DIM + lane * 4];
    float* dst = &g_S[m * DIM + lane * 4];
    asm volatile("red.global.add.v4.f32 [%0], {%1, %2, %3, %4};"
                 :: "l"(dst), "f"(vv.x), "f"(vv.y), "f"(vv.z), "f"(vv.w)
                 : "memory");
    if (lane == 0) atomicAdd(&g_cnt[m], 1.0f);
}

// ---------------- K3: x-direction gaussian contraction ----------------
// thread -> (cx, by, d) with cx and cx+16 sharing all loads. 256 blocks x 256.
__global__ __launch_bounds__(256)
void k_cx(const int* __restrict__ it) {
    __shared__ float e_s[32];
    int t = blockIdx.x * 256 + threadIdx.x;    // 0..65535
    int d   = t & 127;
    int by  = (t >> 7) & 31;
    int cx0 = t >> 12;                          // 0..15
    int cx1 = cx0 + 16;

    float lr_decay = 1.0f - (float)it[0] / NITER_F;
    float sig = SIGMA_F * lr_decay;
    float inv_s2 = 1.0f / (sig * sig);
    if (threadIdx.x < 32)
        e_s[threadIdx.x] = expf(-(float)(threadIdx.x * threadIdx.x) * inv_s2);
    __syncthreads();

    // force MLP=32: preload the whole column
    float sv[32];
    #pragma unroll
    for (int bx = 0; bx < 32; bx++)
        sv[bx] = g_S[(by * 32 + bx) * DIM + d];

    float c0 = 0.f, c1 = 0.f;
    if (d == 0) {
        #pragma unroll
        for (int bx = 0; bx < 32; bx++) {
            float cb = g_cnt[by * 32 + bx];
            c0 += e_s[abs(cx0 - bx)] * cb;
            c1 += e_s[abs(cx1 - bx)] * cb;
        }
        g_tc[cx0 * 32 + by] = c0;
        g_tc[cx1 * 32 + by] = c1;
    }

    float a0 = 0.f, a1 = 0.f;
    #pragma unroll
    for (int bx = 0; bx < 32; bx++) {
        a0 += e_s[abs(cx0 - bx)] * sv[bx];
        a1 += e_s[abs(cx1 - bx)] * sv[bx];
    }
    g_T[(cx0 * 32 + by) * DIM + d] = a0;
    g_T[(cx1 * 32 + by) * DIM + d] = a1;
}

// ---------------- K4: y-direction contraction + final update ----------------
__global__ __launch_bounds__(256)
void k_cy(const float* __restrict__ w,
          const int* __restrict__ it,
          float* __restrict__ out) {
    __shared__ float e_s[32];
    int t = blockIdx.x * 256 + threadIdx.x;    // 0..65535
    int d   = t & 127;
    int cx  = (t >> 7) & 31;
    int cy0 = t >> 12;                          // 0..15
    int cy1 = cy0 + 16;

    float lr_decay = 1.0f - (float)it[0] / NITER_F;
    float alpha_op = ALPHA_F * lr_decay;
    float sig = SIGMA_F * lr_decay;
    float inv_s2 = 1.0f / (sig * sig);
    if (threadIdx.x < 32)
        e_s[threadIdx.x] = expf(-(float)(threadIdx.x * threadIdx.x) * inv_s2);
    __syncthreads();

    float tv[32];
    #pragma unroll
    for (int by = 0; by < 32; by++)
        tv[by] = g_T[(cx * 32 + by) * DIM + d];

    float a0 = 0.f, a1 = 0.f, s0 = 0.f, s1 = 0.f;
    #pragma unroll
    for (int by = 0; by < 32; by++) {
        float e0 = e_s[abs(cy0 - by)];
        float e1 = e_s[abs(cy1 - by)];
        float tc = g_tc[cx * 32 + by];     // broadcast within warp
        a0 += e0 * tv[by];  a1 += e1 * tv[by];
        s0 += e0 * tc;      s1 += e1 * tc;
    }

    int c0 = (cy0 * 32 + cx) * DIM + d;
    int c1 = (cy1 * 32 + cx) * DIM + d;
    float w0 = w[c0], w1 = w[c1];
    out[c0] = w0 + alpha_op * a0 - alpha_op * s0 * w0;
    out[c1] = w1 + alpha_op * a1 - alpha_op * s1 * w1;
}

// ---------------- launch ----------------
extern "C" void kernel_launch(void* const* d_in, const int* in_sizes, int n_in,
                              void* d_out, int out_size) {
    const float* x   = (const float*)d_in[0];   // [2048,128]
    const float* w   = (const float*)d_in[1];   // [1024,128]
    const int*   it  = (const int*)d_in[3];
    float* out = (float*)d_out;

    const int bmu_smem = 2 * 128 * 128 * 4 + 16 * 128 * 8 + 128 * 4;
    cudaFuncSetAttribute(k_bmu, cudaFuncAttributeMaxDynamicSharedMemorySize,
                         bmu_smem);

    k_bmu<<<dim3(8, 16), 256, bmu_smem>>>(x, w);
    k_scatter<<<256, 256>>>(x);
    k_cx<<<256, 256>>>(it);
    k_cy<<<256, 256>>>(w, it, out);
}

// round 5
// speedup vs baseline: 1.3782x; 1.3782x over previous
#include <cuda_runtime.h>
#include <cstdint>

#define SOM_M    32
#define SOM_N    32
#define MN       1024
#define BATCH    2048
#define DIM      128
#define NITER_F  100.0f
#define ALPHA_F  0.3f
#define SIGMA_F  16.0f

// ---------------- scratch ----------------
__device__ unsigned long long g_part[8][BATCH];  // per-m-block argmin partials
__device__ float g_S[MN * DIM];
__device__ float g_cnt[MN];
__device__ float g_T[MN * DIM];          // [cx][by][d]
__device__ float g_tc[MN];               // [cx][by]

__device__ __forceinline__ unsigned int f2ord(float f) {
    unsigned int u = __float_as_uint(f);
    return (u & 0x80000000u) ? ~u : (u | 0x80000000u);
}

__device__ __forceinline__ void ffma2(unsigned long long& acc,
                                      unsigned long long a,
                                      unsigned long long b) {
    asm("fma.rn.f32x2 %0, %1, %2, %0;" : "+l"(acc) : "l"(a), "l"(b));
}

// ---------------- K1: BMU GEMM + argmin (zeroes scratch, computes w2) ------
// tile 128m x 128b, 256 threads, 8m x 8b per thread, FFMA2 pairs along K.
// Smem tiles row-natural with 16B-group XOR swizzle for conflict-free reads.
__global__ __launch_bounds__(256, 1)
void k_bmu(const float* __restrict__ x, const float* __restrict__ w) {
    extern __shared__ float smem[];
    float* Ws = smem;                                   // 128*128 f
    float* Xs = smem + 128 * 128;                       // 128*128 f
    unsigned long long* Red =
        (unsigned long long*)(smem + 2 * 128 * 128);    // [16][128]
    float* w2s = (float*)(Red + 16 * 128);              // [128]

    const int m0 = blockIdx.x * 128;
    const int b0 = blockIdx.y * 128;
    const int tid = threadIdx.x;
    const int wrp = tid >> 5, lane = tid & 31;
    const int ty = (lane >> 2) | ((wrp & 1) << 3);      // 0..15
    const int tx = (lane & 3) | ((wrp >> 1) << 2);      // 0..15

    // fold scratch zeroing into this kernel (completes before k_scatter)
    {
        int z = blockIdx.y * 8 + blockIdx.x;            // 0..127
        *(float4*)&g_S[z * 1024 + tid * 4] = make_float4(0.f, 0.f, 0.f, 0.f);
        if (tid < 2)
            *(float4*)&g_cnt[z * 8 + tid * 4] = make_float4(0.f, 0.f, 0.f, 0.f);
    }

    // stage both tiles (LDG.128 -> swizzled ST.128)
    #pragma unroll
    for (int i = 0; i < 16; i++) {
        int idx = tid + i * 256;          // 0..4095
        int row = idx >> 5;               // 0..127
        int g   = idx & 31;               // float4 group
        int sg  = (g ^ ((row >> 3) & 7)) << 2;
        float4 v = *(const float4*)&w[(m0 + row) * DIM + g * 4];
        *(float4*)&Ws[row * 128 + sg] = v;
        float4 u = *(const float4*)&x[(b0 + row) * DIM + g * 4];
        *(float4*)&Xs[row * 128 + sg] = u;
    }
    __syncthreads();

    // w2 from the staged tile (swizzle is a within-row permutation)
    if (tid < 128) {
        float s = 0.0f;
        #pragma unroll
        for (int g = 0; g < 32; g++) {
            float4 v = *(const float4*)&Ws[tid * 128 + g * 4];
            s += v.x * v.x + v.y * v.y + v.z * v.z + v.w * v.w;
        }
        w2s[tid] = s;
    }

    unsigned long long acc[8][8];
    #pragma unroll
    for (int mi = 0; mi < 8; mi++)
        #pragma unroll
        for (int bj = 0; bj < 8; bj++) acc[mi][bj] = 0ULL;

    const float* wbase = &Ws[(ty * 8) * 128];
    const float* xbase = &Xs[(tx * 8) * 128];
    const int sw = ty & 7;
    const int sx = tx & 7;

    #pragma unroll 1
    for (int kt = 0; kt < 32; kt++) {      // 4 k per step
        const int ow = (kt ^ sw) << 2;
        const int ox = (kt ^ sx) << 2;
        ulonglong2 xv[8];
        #pragma unroll
        for (int bj = 0; bj < 8; bj++)
            xv[bj] = *(const ulonglong2*)&xbase[bj * 128 + ox];
        #pragma unroll
        for (int mi = 0; mi < 8; mi++) {
            ulonglong2 wv = *(const ulonglong2*)&wbase[mi * 128 + ow];
            #pragma unroll
            for (int bj = 0; bj < 8; bj++) {
                ffma2(acc[mi][bj], wv.x, xv[bj].x);
                ffma2(acc[mi][bj], wv.y, xv[bj].y);
            }
        }
    }
    __syncthreads();   // w2s ready

    float w2r[8];
    #pragma unroll
    for (int mi = 0; mi < 8; mi++) w2r[mi] = w2s[ty * 8 + mi];

    #pragma unroll
    for (int bj = 0; bj < 8; bj++) {
        unsigned long long best = 0xFFFFFFFFFFFFFFFFULL;
        #pragma unroll
        for (int mi = 0; mi < 8; mi++) {
            float lo = __uint_as_float((unsigned int)(acc[mi][bj]));
            float hi = __uint_as_float((unsigned int)(acc[mi][bj] >> 32));
            float d2 = w2r[mi] - 2.0f * (lo + hi);
            unsigned long long key =
                ((unsigned long long)f2ord(d2) << 32) |
                (unsigned long long)(m0 + ty * 8 + mi);
            best = min(best, key);
        }
        Red[ty * 128 + tx * 8 + bj] = best;
    }
    __syncthreads();

    if (tid < 128) {
        unsigned long long best = Red[tid];
        #pragma unroll
        for (int t = 1; t < 16; t++) best = min(best, Red[t * 128 + tid]);
        g_part[blockIdx.x][b0 + tid] = best;   // plain store, no atomics
    }
}

// ---------------- K2: reduce partials + scatter x rows into BMU bins --------
__global__ void k_scatter(const float* __restrict__ x) {
    int warp = (blockIdx.x * blockDim.x + threadIdx.x) >> 5;  // 0..2047
    int lane = threadIdx.x & 31;
    if (warp >= BATCH) return;

    unsigned long long v = (lane < 8) ? g_part[lane][warp]
                                      : 0xFFFFFFFFFFFFFFFFULL;
    #pragma unroll
    for (int o = 4; o >= 1; o >>= 1)
        v = min(v, __shfl_xor_sync(0xffffffffu, v, o));
    v = __shfl_sync(0xffffffffu, v, 0);
    int m = (int)(v & 0xFFFFFFFFULL);

    float4 vv = *(const float4*)&x[warp * DIM + lane * 4];
    float* dst = &g_S[m * DIM + lane * 4];
    asm volatile("red.global.add.v4.f32 [%0], {%1, %2, %3, %4};"
                 :: "l"(dst), "f"(vv.x), "f"(vv.y), "f"(vv.z), "f"(vv.w)
                 : "memory");
    if (lane == 0) atomicAdd(&g_cnt[m], 1.0f);
}

// ---------------- K3: x-direction gaussian contraction ----------------
// 8192 threads: t -> (d4 0..31, by 0..31, cxg 0..7); 4 cx outputs share all
// loads. All traffic LDG.128/ST.128, coalesced over d4 within the warp.
__global__ __launch_bounds__(128)
void k_cx(const int* __restrict__ it) {
    __shared__ float e_s[32];
    const int t   = blockIdx.x * 128 + threadIdx.x;   // 0..8191
    const int d4  = t & 31;
    const int by  = (t >> 5) & 31;
    const int cx0 = (t >> 10) * 4;

    float lr_decay = 1.0f - (float)it[0] / NITER_F;
    float sig = SIGMA_F * lr_decay;
    float inv_s2 = 1.0f / (sig * sig);
    if (threadIdx.x < 32)
        e_s[threadIdx.x] = expf(-(float)(threadIdx.x * threadIdx.x) * inv_s2);
    __syncthreads();

    float4 a0 = {0,0,0,0}, a1 = {0,0,0,0}, a2 = {0,0,0,0}, a3 = {0,0,0,0};
    float c0 = 0.f, c1 = 0.f, c2 = 0.f, c3 = 0.f;

    #pragma unroll
    for (int bb = 0; bb < 4; bb++) {
        float4 sv[8];
        float  cv[8];
        #pragma unroll
        for (int j = 0; j < 8; j++) {
            int bx = bb * 8 + j;
            sv[j] = *(const float4*)&g_S[(by * 32 + bx) * DIM + d4 * 4];
            cv[j] = g_cnt[by * 32 + bx];
        }
        #pragma unroll
        for (int j = 0; j < 8; j++) {
            int bx = bb * 8 + j;
            float e0 = e_s[abs(cx0 + 0 - bx)];
            float e1 = e_s[abs(cx0 + 1 - bx)];
            float e2 = e_s[abs(cx0 + 2 - bx)];
            float e3 = e_s[abs(cx0 + 3 - bx)];
            a0.x += e0 * sv[j].x; a0.y += e0 * sv[j].y;
            a0.z += e0 * sv[j].z; a0.w += e0 * sv[j].w;
            a1.x += e1 * sv[j].x; a1.y += e1 * sv[j].y;
            a1.z += e1 * sv[j].z; a1.w += e1 * sv[j].w;
            a2.x += e2 * sv[j].x; a2.y += e2 * sv[j].y;
            a2.z += e2 * sv[j].z; a2.w += e2 * sv[j].w;
            a3.x += e3 * sv[j].x; a3.y += e3 * sv[j].y;
            a3.z += e3 * sv[j].z; a3.w += e3 * sv[j].w;
            c0 += e0 * cv[j]; c1 += e1 * cv[j];
            c2 += e2 * cv[j]; c3 += e3 * cv[j];
        }
    }
    *(float4*)&g_T[((cx0 + 0) * 32 + by) * DIM + d4 * 4] = a0;
    *(float4*)&g_T[((cx0 + 1) * 32 + by) * DIM + d4 * 4] = a1;
    *(float4*)&g_T[((cx0 + 2) * 32 + by) * DIM + d4 * 4] = a2;
    *(float4*)&g_T[((cx0 + 3) * 32 + by) * DIM + d4 * 4] = a3;
    if (d4 == 0) {
        g_tc[(cx0 + 0) * 32 + by] = c0;
        g_tc[(cx0 + 1) * 32 + by] = c1;
        g_tc[(cx0 + 2) * 32 + by] = c2;
        g_tc[(cx0 + 3) * 32 + by] = c3;
    }
}

// ---------------- K4: y-direction contraction + final update ----------------
// 8192 threads: t -> (d4, cx, cyg); 4 cy outputs share all loads.
__global__ __launch_bounds__(128)
void k_cy(const float* __restrict__ w,
          const int* __restrict__ it,
          float* __restrict__ out) {
    __shared__ float e_s[32];
    const int t   = blockIdx.x * 128 + threadIdx.x;   // 0..8191
    const int d4  = t & 31;
    const int cx  = (t >> 5) & 31;
    const int cy0 = (t >> 10) * 4;

    float lr_decay = 1.0f - (float)it[0] / NITER_F;
    float alpha_op = ALPHA_F * lr_decay;
    float sig = SIGMA_F * lr_decay;
    float inv_s2 = 1.0f / (sig * sig);
    if (threadIdx.x < 32)
        e_s[threadIdx.x] = expf(-(float)(threadIdx.x * threadIdx.x) * inv_s2);
    __syncthreads();

    float4 a0 = {0,0,0,0}, a1 = {0,0,0,0}, a2 = {0,0,0,0}, a3 = {0,0,0,0};
    float s0 = 0.f, s1 = 0.f, s2 = 0.f, s3 = 0.f;

    #pragma unroll
    for (int bb = 0; bb < 4; bb++) {
        float4 tv[8];
        float  cv[8];
        #pragma unroll
        for (int j = 0; j < 8; j++) {
            int by = bb * 8 + j;
            tv[j] = *(const float4*)&g_T[(cx * 32 + by) * DIM + d4 * 4];
            cv[j] = g_tc[cx * 32 + by];    // warp-uniform broadcast
        }
        #pragma unroll
        for (int j = 0; j < 8; j++) {
            int by = bb * 8 + j;
            float e0 = e_s[abs(cy0 + 0 - by)];
            float e1 = e_s[abs(cy0 + 1 - by)];
            float e2 = e_s[abs(cy0 + 2 - by)];
            float e3 = e_s[abs(cy0 + 3 - by)];
            a0.x += e0 * tv[j].x; a0.y += e0 * tv[j].y;
            a0.z += e0 * tv[j].z; a0.w += e0 * tv[j].w;
            a1.x += e1 * tv[j].x; a1.y += e1 * tv[j].y;
            a1.z += e1 * tv[j].z; a1.w += e1 * tv[j].w;
            a2.x += e2 * tv[j].x; a2.y += e2 * tv[j].y;
            a2.z += e2 * tv[j].z; a2.w += e2 * tv[j].w;
            a3.x += e3 * tv[j].x; a3.y += e3 * tv[j].y;
            a3.z += e3 * tv[j].z; a3.w += e3 * tv[j].w;
            s0 += e0 * cv[j]; s1 += e1 * cv[j];
            s2 += e2 * cv[j]; s3 += e3 * cv[j];
        }
    }

    #pragma unroll
    for (int q = 0; q < 4; q++) {
        float4 aq = (q == 0) ? a0 : (q == 1) ? a1 : (q == 2) ? a2 : a3;
        float  sq = (q == 0) ? s0 : (q == 1) ? s1 : (q == 2) ? s2 : s3;
        int c = ((cy0 + q) * 32 + cx) * DIM + d4 * 4;
        float4 wv = *(const float4*)&w[c];
        float4 o;
        o.x = wv.x + alpha_op * (aq.x - sq * wv.x);
        o.y = wv.y + alpha_op * (aq.y - sq * wv.y);
        o.z = wv.z + alpha_op * (aq.z - sq * wv.z);
        o.w = wv.w + alpha_op * (aq.w - sq * wv.w);
        *(float4*)&out[c] = o;
    }
}

// ---------------- launch ----------------
extern "C" void kernel_launch(void* const* d_in, const int* in_sizes, int n_in,
                              void* d_out, int out_size) {
    const float* x   = (const float*)d_in[0];   // [2048,128]
    const float* w   = (const float*)d_in[1];   // [1024,128]
    const int*   it  = (const int*)d_in[3];
    float* out = (float*)d_out;

    const int bmu_smem = 2 * 128 * 128 * 4 + 16 * 128 * 8 + 128 * 4;
    cudaFuncSetAttribute(k_bmu, cudaFuncAttributeMaxDynamicSharedMemorySize,
                         bmu_smem);

    k_bmu<<<dim3(8, 16), 256, bmu_smem>>>(x, w);
    k_scatter<<<256, 256>>>(x);
    k_cx<<<64, 128>>>(it);
    k_cy<<<64, 128>>>(w, it, out);
}

// round 6
// speedup vs baseline: 1.5582x; 1.1306x over previous
#include <cuda_runtime.h>
#include <cstdint>

#define SOM_M    32
#define SOM_N    32
#define MN       1024
#define BATCH    2048
#define DIM      128
#define NITER_F  100.0f
#define ALPHA_F  0.3f
#define SIGMA_F  16.0f

// ---------------- scratch ----------------
__device__ unsigned long long g_part[8][BATCH];  // per-m-block argmin partials
__device__ float g_S[MN * DIM];
__device__ float g_cnt[MN];

__device__ __forceinline__ unsigned int f2ord(float f) {
    unsigned int u = __float_as_uint(f);
    return (u & 0x80000000u) ? ~u : (u | 0x80000000u);
}

__device__ __forceinline__ void ffma2(unsigned long long& acc,
                                      unsigned long long a,
                                      unsigned long long b) {
    asm("fma.rn.f32x2 %0, %1, %2, %0;" : "+l"(acc) : "l"(a), "l"(b));
}

// ---------------- K1: BMU GEMM + argmin (zeroes scratch, computes w2) ------
// tile 128m x 128b, 256 threads, 8m x 8b per thread, FFMA2 pairs along K.
// Smem tiles row-natural with 16B-group XOR swizzle for conflict-free reads.
__global__ __launch_bounds__(256, 1)
void k_bmu(const float* __restrict__ x, const float* __restrict__ w) {
    extern __shared__ float smem[];
    float* Ws = smem;                                   // 128*128 f
    float* Xs = smem + 128 * 128;                       // 128*128 f
    unsigned long long* Red =
        (unsigned long long*)(smem + 2 * 128 * 128);    // [16][128]
    float* w2s = (float*)(Red + 16 * 128);              // [128]

    const int m0 = blockIdx.x * 128;
    const int b0 = blockIdx.y * 128;
    const int tid = threadIdx.x;
    const int wrp = tid >> 5, lane = tid & 31;
    const int ty = (lane >> 2) | ((wrp & 1) << 3);      // 0..15
    const int tx = (lane & 3) | ((wrp >> 1) << 2);      // 0..15

    // fold scratch zeroing into this kernel (completes before k_scatter)
    {
        int z = blockIdx.y * 8 + blockIdx.x;            // 0..127
        *(float4*)&g_S[z * 1024 + tid * 4] = make_float4(0.f, 0.f, 0.f, 0.f);
        if (tid < 2)
            *(float4*)&g_cnt[z * 8 + tid * 4] = make_float4(0.f, 0.f, 0.f, 0.f);
    }

    // stage both tiles (LDG.128 -> swizzled ST.128)
    #pragma unroll
    for (int i = 0; i < 16; i++) {
        int idx = tid + i * 256;          // 0..4095
        int row = idx >> 5;               // 0..127
        int g   = idx & 31;               // float4 group
        int sg  = (g ^ ((row >> 3) & 7)) << 2;
        float4 v = *(const float4*)&w[(m0 + row) * DIM + g * 4];
        *(float4*)&Ws[row * 128 + sg] = v;
        float4 u = *(const float4*)&x[(b0 + row) * DIM + g * 4];
        *(float4*)&Xs[row * 128 + sg] = u;
    }
    __syncthreads();

    // w2 from the staged tile (swizzle is a within-row permutation)
    if (tid < 128) {
        float s = 0.0f;
        #pragma unroll
        for (int g = 0; g < 32; g++) {
            float4 v = *(const float4*)&Ws[tid * 128 + g * 4];
            s += v.x * v.x + v.y * v.y + v.z * v.z + v.w * v.w;
        }
        w2s[tid] = s;
    }

    unsigned long long acc[8][8];
    #pragma unroll
    for (int mi = 0; mi < 8; mi++)
        #pragma unroll
        for (int bj = 0; bj < 8; bj++) acc[mi][bj] = 0ULL;

    const float* wbase = &Ws[(ty * 8) * 128];
    const float* xbase = &Xs[(tx * 8) * 128];
    const int sw = ty & 7;
    const int sx = tx & 7;

    #pragma unroll 1
    for (int kt = 0; kt < 32; kt++) {      // 4 k per step
        const int ow = (kt ^ sw) << 2;
        const int ox = (kt ^ sx) << 2;
        ulonglong2 xv[8];
        #pragma unroll
        for (int bj = 0; bj < 8; bj++)
            xv[bj] = *(const ulonglong2*)&xbase[bj * 128 + ox];
        #pragma unroll
        for (int mi = 0; mi < 8; mi++) {
            ulonglong2 wv = *(const ulonglong2*)&wbase[mi * 128 + ow];
            #pragma unroll
            for (int bj = 0; bj < 8; bj++) {
                ffma2(acc[mi][bj], wv.x, xv[bj].x);
                ffma2(acc[mi][bj], wv.y, xv[bj].y);
            }
        }
    }
    __syncthreads();   // w2s ready

    float w2r[8];
    #pragma unroll
    for (int mi = 0; mi < 8; mi++) w2r[mi] = w2s[ty * 8 + mi];

    #pragma unroll
    for (int bj = 0; bj < 8; bj++) {
        unsigned long long best = 0xFFFFFFFFFFFFFFFFULL;
        #pragma unroll
        for (int mi = 0; mi < 8; mi++) {
            float lo = __uint_as_float((unsigned int)(acc[mi][bj]));
            float hi = __uint_as_float((unsigned int)(acc[mi][bj] >> 32));
            float d2 = w2r[mi] - 2.0f * (lo + hi);
            unsigned long long key =
                ((unsigned long long)f2ord(d2) << 32) |
                (unsigned long long)(m0 + ty * 8 + mi);
            best = min(best, key);
        }
        Red[ty * 128 + tx * 8 + bj] = best;
    }
    __syncthreads();

    if (tid < 128) {
        unsigned long long best = Red[tid];
        #pragma unroll
        for (int t = 1; t < 16; t++) best = min(best, Red[t * 128 + tid]);
        g_part[blockIdx.x][b0 + tid] = best;   // plain store, no atomics
    }
}

// ---------------- K2: reduce partials + scatter x rows into BMU bins --------
__global__ void k_scatter(const float* __restrict__ x) {
    int warp = (blockIdx.x * blockDim.x + threadIdx.x) >> 5;  // 0..2047
    int lane = threadIdx.x & 31;
    if (warp >= BATCH) return;

    unsigned long long v = (lane < 8) ? g_part[lane][warp]
                                      : 0xFFFFFFFFFFFFFFFFULL;
    #pragma unroll
    for (int o = 4; o >= 1; o >>= 1)
        v = min(v, __shfl_xor_sync(0xffffffffu, v, o));
    v = __shfl_sync(0xffffffffu, v, 0);
    int m = (int)(v & 0xFFFFFFFFULL);

    float4 vv = *(const float4*)&x[warp * DIM + lane * 4];
    float* dst = &g_S[m * DIM + lane * 4];
    asm volatile("red.global.add.v4.f32 [%0], {%1, %2, %3, %4};"
                 :: "l"(dst), "f"(vv.x), "f"(vv.y), "f"(vv.z), "f"(vv.w)
                 : "memory");
    if (lane == 0) atomicAdd(&g_cnt[m], 1.0f);
}

// ---------------- K3: fused separable gaussian contraction + update ---------
// 128 blocks = (cx, d-quarter), 256 threads.
// stage A: Ts[by][d] = sum_bx e(|cx-bx|) * S[by*32+bx][d]  (batched preloads)
// stage B: out[cy*32+cx][d] = w + alpha*(sum_by e*Ts - (sum_by e*tc)*w)
__global__ __launch_bounds__(256)
void k_tail(const float* __restrict__ w,
            const int* __restrict__ it,
            float* __restrict__ out) {
    __shared__ float4 Ts[32][9];     // [by][dq], padded: stride 9 float4s
    __shared__ float tc_s[32];
    __shared__ float e_s[32];

    const int cx = blockIdx.x & 31;
    const int d0 = (blockIdx.x >> 5) * 32;   // d-quarter base
    const int tid = threadIdx.x;

    float lr_decay = 1.0f - (float)it[0] / NITER_F;
    float alpha_op = ALPHA_F * lr_decay;
    float sig = SIGMA_F * lr_decay;
    float inv_s2 = 1.0f / (sig * sig);

    if (tid < 32) e_s[tid] = expf(-(float)(tid * tid) * inv_s2);
    __syncthreads();

    // stage A
    {
        const int by = tid >> 3;           // 0..31
        const int dq = tid & 7;            // float4 index 0..7
        const int d  = d0 + dq * 4;
        float4 a = make_float4(0.f, 0.f, 0.f, 0.f);
        #pragma unroll
        for (int bb = 0; bb < 4; bb++) {
            float4 sv[8];
            #pragma unroll
            for (int j = 0; j < 8; j++)
                sv[j] = *(const float4*)&g_S[(by * 32 + bb * 8 + j) * DIM + d];
            #pragma unroll
            for (int j = 0; j < 8; j++) {
                float e = e_s[abs(cx - (bb * 8 + j))];
                a.x += e * sv[j].x; a.y += e * sv[j].y;
                a.z += e * sv[j].z; a.w += e * sv[j].w;
            }
        }
        Ts[by][dq] = a;
    }
    if (tid < 32) {
        float c = 0.0f;
        #pragma unroll
        for (int bx = 0; bx < 32; bx++)
            c += e_s[abs(cx - bx)] * g_cnt[tid * 32 + bx];
        tc_s[tid] = c;
    }
    __syncthreads();

    // stage B
    {
        const int cy = tid >> 3;
        const int dq = tid & 7;
        const int d  = d0 + dq * 4;
        float4 a = make_float4(0.f, 0.f, 0.f, 0.f);
        float s = 0.0f;
        #pragma unroll
        for (int by = 0; by < 32; by++) {
            float e = e_s[abs(cy - by)];
            float4 t = Ts[by][dq];
            a.x += e * t.x; a.y += e * t.y;
            a.z += e * t.z; a.w += e * t.w;
            s += e * tc_s[by];
        }
        const int c = (cy * 32 + cx) * DIM + d;
        float4 wv = *(const float4*)&w[c];
        float4 o;
        o.x = wv.x + alpha_op * (a.x - s * wv.x);
        o.y = wv.y + alpha_op * (a.y - s * wv.y);
        o.z = wv.z + alpha_op * (a.z - s * wv.z);
        o.w = wv.w + alpha_op * (a.w - s * wv.w);
        *(float4*)&out[c] = o;
    }
}

// ---------------- launch ----------------
extern "C" void kernel_launch(void* const* d_in, const int* in_sizes, int n_in,
                              void* d_out, int out_size) {
    const float* x   = (const float*)d_in[0];   // [2048,128]
    const float* w   = (const float*)d_in[1];   // [1024,128]
    const int*   it  = (const int*)d_in[3];
    float* out = (float*)d_out;

    const int bmu_smem = 2 * 128 * 128 * 4 + 16 * 128 * 8 + 128 * 4;
    cudaFuncSetAttribute(k_bmu, cudaFuncAttributeMaxDynamicSharedMemorySize,
                         bmu_smem);

    k_bmu<<<dim3(8, 16), 256, bmu_smem>>>(x, w);
    k_scatter<<<256, 256>>>(x);
    k_tail<<<128, 256>>>(w, it, out);
}